// round 9
// baseline (speedup 1.0000x reference)
#include <cuda_runtime.h>
#include <math.h>

#define N_NODES 50000
#define N_EDGES 600000
#define N_GRAPHS 64

static __device__ float g_fa[N_NODES * 64];
static __device__ float g_fb[N_NODES * 64];
static __device__ float g_F [N_NODES * 64];

#define INV_S3 0.57735026918962576f   /* 1/sqrt(3) */
#define INV_S2 0.70710678118654752f   /* 1/sqrt(2) */
#define NORM_S 0.044194173824159216f  /* 1/sqrt(512) */
#define NORM_V 0.036084391824351615f  /* 1/sqrt(768) */
#define INV_LIN_IN 0.35355339059327373f /* 1/sqrt(8) */
#define INV_LIN_OUT 0.25f

typedef unsigned long long u64;

// ---- packed fp32x2 helpers (sm_103a) --------------------------------------
__device__ __forceinline__ u64 pack2f(float a, float b) {
    u64 r;
    asm("mov.b64 %0, {%1, %2};" : "=l"(r) : "f"(a), "f"(b));
    return r;
}
__device__ __forceinline__ void unpack2f(float& a, float& b, u64 p) {
    asm("mov.b64 {%0, %1}, %2;" : "=f"(a), "=f"(b) : "l"(p));
}
__device__ __forceinline__ u64 ffma2(u64 a, u64 b, u64 c) {
    u64 d;
    asm("fma.rn.f32x2 %0, %1, %2, %3;" : "=l"(d) : "l"(a), "l"(b), "l"(c));
    return d;
}
__device__ __forceinline__ u64 addf2(u64 a, u64 b) {
    u64 d;
    asm("add.rn.f32x2 %0, %1, %2;" : "=l"(d) : "l"(a), "l"(b));
    return d;
}
__device__ __forceinline__ u64 neg2(u64 a) { return a ^ 0x8000000080000000ULL; }

// ---------------------------------------------------------------------------
// Input projection: x[N,32] -> f[N,64]  (s[16] | v[16][3] at 16+w*3+i)
// ---------------------------------------------------------------------------
__global__ __launch_bounds__(256) void proj_kernel(
    const float* __restrict__ x, const float* __restrict__ w0,
    const float* __restrict__ w1, float* __restrict__ f)
{
    __shared__ float sw0[128], sw1[128];
    int t = threadIdx.x;
    if (t < 128) sw0[t] = w0[t];
    else         sw1[t - 128] = w1[t - 128];
    __syncthreads();

    int n = blockIdx.x * 256 + t;
    if (n >= N_NODES) return;

    float xin[32];
    #pragma unroll
    for (int i = 0; i < 8; ++i)
        ((float4*)xin)[i] = ((const float4*)(x + n * 32))[i];

    float s[16];
    #pragma unroll
    for (int w = 0; w < 16; ++w) s[w] = 0.f;
    #pragma unroll
    for (int u = 0; u < 8; ++u) {
        float xu = xin[u];
        #pragma unroll
        for (int w = 0; w < 16; ++w) s[w] += xu * sw0[u * 16 + w];
    }
    float vv[48];
    #pragma unroll
    for (int q = 0; q < 48; ++q) vv[q] = 0.f;
    #pragma unroll
    for (int u = 0; u < 8; ++u) {
        float x0 = xin[8 + u * 3 + 0];
        float x1 = xin[8 + u * 3 + 1];
        float x2 = xin[8 + u * 3 + 2];
        #pragma unroll
        for (int w = 0; w < 16; ++w) {
            float wt = sw1[u * 16 + w];
            vv[w * 3 + 0] += x0 * wt;
            vv[w * 3 + 1] += x1 * wt;
            vv[w * 3 + 2] += x2 * wt;
        }
    }
    float* fn = f + n * 64;
    #pragma unroll
    for (int w = 0; w < 16; ++w) fn[w] = s[w] * INV_LIN_IN;
    #pragma unroll
    for (int q = 0; q < 48; ++q) fn[16 + q] = vv[q] * INV_LIN_IN;
}

// ---------------------------------------------------------------------------
// Aggregation: F[row[e]] += f[col[e]] via red.global.v4.f32.add (REDG.128)
// ---------------------------------------------------------------------------
__global__ __launch_bounds__(256) void agg_kernel(
    const float* __restrict__ f, const int* __restrict__ row,
    const int* __restrict__ col, float* __restrict__ F)
{
    unsigned idx = blockIdx.x * 256u + threadIdx.x;
    unsigned e = idx >> 4, q = idx & 15u;
    if (e >= N_EDGES) return;
    int c = __ldg(col + e);
    int r = __ldg(row + e);
    float4 val = ((const float4*)(f + (size_t)c * 64))[q];
    float* dst = F + (size_t)r * 64 + q * 4;
    asm volatile("red.global.v4.f32.add [%0], {%1, %2, %3, %4};"
                 :: "l"(dst), "f"(val.x), "f"(val.y), "f"(val.z), "f"(val.w)
                 : "memory");
}

// ---------------------------------------------------------------------------
// Per-node TP + gate, (v,w)-pair packed.
// Thread t7 = v*8 + wp covers outputs (v, 2wp) and (v, 2wp+1) in one f32x2 lane
// pair. Weights for paths 0,1 in registers (u64 = contiguous w-pair), paths
// 2,3,4 in smem. Features duplicate-packed (x,x) in smem, read via broadcast.
// Block = 2 independent 128-thread groups (named barriers), 2 nodes per group
// iteration.
// ---------------------------------------------------------------------------
#define NPG 2  /* nodes per group iteration */

#define SM_WSM   0                        /* u64[3][16][128] = 6144 */
#define SM_SFD   6144                     /* u64[2][NPG][128] = 512 */
#define SM_TSP   (6144 + 512)             /* u64[2][NPG][11][128] = 5632 */
#define SM_OUTF  (6144 + 512 + 5632)      /* float[2][NPG][64] = 256 f = 128 u64 */
#define SM_U64S  (6144 + 512 + 5632 + 128)
#define SM_BYTES (SM_U64S * 8)

__global__ __launch_bounds__(256, 2) void tp_gate_kernel(
    const float* __restrict__ f, const float* __restrict__ Fg,
    const float* __restrict__ W, float* __restrict__ fout)
{
    extern __shared__ u64 dsm[];
    u64*   wsm  = dsm + SM_WSM;
    u64*   sfd  = dsm + SM_SFD;
    u64*   tsp  = dsm + SM_TSP;
    float* outf = (float*)(dsm + SM_OUTF);

    const int tid = threadIdx.x;
    const int g   = tid >> 7;     // group 0/1
    const int t7  = tid & 127;

    // ---- weight preload ----
    // paths 0,1 -> registers; W[p][u][v][w] w-fastest: float2 idx = p*2048+u*128+t7
    const float2* Wf2 = (const float2*)W;
    u64 w0r[16], w1r[16];
    #pragma unroll
    for (int u = 0; u < 16; ++u) {
        float2 a = __ldg(Wf2 + 0 * 2048 + u * 128 + t7);
        float2 b = __ldg(Wf2 + 1 * 2048 + u * 128 + t7);
        w0r[u] = pack2f(a.x, a.y);
        w1r[u] = pack2f(b.x, b.y);
    }
    // paths 2,3,4 -> smem: wsm[(p2*16+u)*128 + j]
    for (int idx = tid; idx < 3 * 16 * 128; idx += 256) {
        int p2 = idx >> 11;          // /2048
        int rem = idx & 2047;
        float2 a = __ldg(Wf2 + (p2 + 2) * 2048 + rem);
        wsm[idx] = pack2f(a.x, a.y);
    }
    __syncthreads();

    const u64 INV3p = pack2f(INV_S3, INV_S3);
    const u64 INV2p = pack2f(INV_S2, INV_S2);

    for (int base = blockIdx.x * (2 * NPG) + g * NPG; base < N_NODES;
         base += gridDim.x * 2 * NPG) {

        // ---- feature load: duplicate-pack 128 comps per node ----
        #pragma unroll
        for (int k = 0; k < NPG; ++k) {
            int node = base + k;
            float val = (t7 < 64) ? f[(size_t)node * 64 + t7]
                                  : Fg[(size_t)node * 64 + (t7 - 64)];
            sfd[(g * NPG + k) * 128 + t7] = pack2f(val, val);
        }
        asm volatile("bar.sync %0, 128;" :: "r"(g + 1) : "memory");

        // ---- stage 1: 11 left contractions per node ----
        #pragma unroll
        for (int k = 0; k < NPG; ++k) {
            const u64* fp = sfd + (g * NPG + k) * 128;
            u64 a0 = 0, a1 = 0;
            u64 a2x = 0, a2y = 0, a2z = 0;
            u64 a3x = 0, a3y = 0, a3z = 0;
            u64 a4x = 0, a4y = 0, a4z = 0;
            #pragma unroll
            for (int u = 0; u < 16; ++u) {
                u64 su = fp[u];
                u64 vx = fp[16 + u * 3 + 0];
                u64 vy = fp[16 + u * 3 + 1];
                u64 vz = fp[16 + u * 3 + 2];
                u64 w2 = wsm[(0 * 16 + u) * 128 + t7];
                u64 w3 = wsm[(1 * 16 + u) * 128 + t7];
                u64 w4 = wsm[(2 * 16 + u) * 128 + t7];
                a0  = ffma2(su, w0r[u], a0);
                a1  = ffma2(su, w1r[u], a1);
                a2x = ffma2(vx, w2, a2x);
                a2y = ffma2(vy, w2, a2y);
                a2z = ffma2(vz, w2, a2z);
                a3x = ffma2(vx, w3, a3x);
                a3y = ffma2(vy, w3, a3y);
                a3z = ffma2(vz, w3, a3z);
                a4x = ffma2(vx, w4, a4x);
                a4y = ffma2(vy, w4, a4y);
                a4z = ffma2(vz, w4, a4z);
            }
            u64* tp = tsp + (g * NPG + k) * 11 * 128;
            tp[0 * 128 + t7] = a0;  tp[1 * 128 + t7] = a1;
            tp[2 * 128 + t7] = a2x; tp[3 * 128 + t7] = a2y; tp[4 * 128 + t7] = a2z;
            tp[5 * 128 + t7] = a3x; tp[6 * 128 + t7] = a3y; tp[7 * 128 + t7] = a3z;
            tp[8 * 128 + t7] = a4x; tp[9 * 128 + t7] = a4y; tp[10 * 128 + t7] = a4z;
        }
        asm volatile("bar.sync %0, 128;" :: "r"(g + 1) : "memory");

        // ---- stage 2: 32 output-pairs per node, 4 threads each ----
        {
            const int op = t7 >> 2, q = t7 & 3;
            #pragma unroll
            for (int k = 0; k < NPG; ++k) {
                const u64* SD = sfd + (g * NPG + k) * 128 + 64;
                const u64* VD = sfd + (g * NPG + k) * 128 + 80;
                const u64* tp = tsp + (g * NPG + k) * 11 * 128;
                u64 acc = 0;
                if (op < 8) {
                    const int wp2 = op;
                    u64 accd = 0;
                    #pragma unroll
                    for (int dv = 0; dv < 4; ++dv) {
                        int v = q * 4 + dv;
                        int ti = v * 8 + wp2;
                        acc  = ffma2(tp[0 * 128 + ti], SD[v], acc);
                        accd = ffma2(tp[5 * 128 + ti], VD[v * 3 + 0], accd);
                        accd = ffma2(tp[6 * 128 + ti], VD[v * 3 + 1], accd);
                        accd = ffma2(tp[7 * 128 + ti], VD[v * 3 + 2], accd);
                    }
                    acc = ffma2(accd, INV3p, acc);
                } else {
                    const int vo = op - 8;
                    const int wp2 = vo / 3, kk = vo % 3;
                    const int i = (kk + 1) % 3, j = (kk + 2) % 3;
                    u64 acc5 = 0;
                    #pragma unroll
                    for (int dv = 0; dv < 4; ++dv) {
                        int v = q * 4 + dv;
                        int ti = v * 8 + wp2;
                        acc  = ffma2(tp[1 * 128 + ti], VD[v * 3 + kk], acc);
                        acc  = ffma2(tp[(2 + kk) * 128 + ti], SD[v], acc);
                        acc5 = ffma2(tp[(8 + i) * 128 + ti], VD[v * 3 + j], acc5);
                        acc5 = ffma2(neg2(tp[(8 + j) * 128 + ti]), VD[v * 3 + i], acc5);
                    }
                    acc = ffma2(acc5, INV2p, acc);
                }
                acc = addf2(acc, __shfl_xor_sync(0xffffffffu, acc, 1));
                acc = addf2(acc, __shfl_xor_sync(0xffffffffu, acc, 2));
                if (q == 0) {
                    float lo, hi;
                    unpack2f(lo, hi, acc);
                    float* ob = outf + (g * NPG + k) * 64;
                    if (op < 8) {
                        ob[2 * op]     = lo;
                        ob[2 * op + 1] = hi;
                    } else {
                        const int vo = op - 8;
                        const int wp2 = vo / 3, kk = vo % 3;
                        ob[16 + (2 * wp2) * 3 + kk]     = lo;
                        ob[16 + (2 * wp2 + 1) * 3 + kk] = hi;
                    }
                }
            }
        }
        asm volatile("bar.sync %0, 128;" :: "r"(g + 1) : "memory");

        // ---- gate + writeback: 2 nodes x 64 outputs = 128 threads ----
        {
            const int k = t7 >> 6, oo = t7 & 63;
            const float* ob = outf + (g * NPG + k) * 64;
            float raw = ob[oo];
            float r;
            if (oo < 16) {
                float sp = NORM_S * raw;
                float sg = 1.f / (1.f + expf(-sp));
                r = sp * sg;
            } else {
                int w = (oo - 16) / 3;
                float sp = NORM_S * ob[w];
                float sg = 1.f / (1.f + expf(-sp));
                r = NORM_V * raw * sg;
            }
            fout[(size_t)(base + k) * 64 + oo] = r;
        }
        asm volatile("bar.sync %0, 128;" :: "r"(g + 1) : "memory");
    }
}

// ---------------------------------------------------------------------------
// Readout: energy[g] = sum_n (s[n]·w_out) * 0.25   grouped by batch_idx
// ---------------------------------------------------------------------------
__global__ __launch_bounds__(256) void readout_kernel(
    const float* __restrict__ f, const int* __restrict__ batch,
    const float* __restrict__ w, float* __restrict__ out)
{
    __shared__ float acc[N_GRAPHS];
    __shared__ float sw[16];
    int t = threadIdx.x;
    if (t < N_GRAPHS) acc[t] = 0.f;
    if (t < 16) sw[t] = w[t];
    __syncthreads();
    int n = blockIdx.x * 256 + t;
    if (n < N_NODES) {
        const float* fn = f + (size_t)n * 64;
        float val = 0.f;
        #pragma unroll
        for (int u = 0; u < 16; ++u) val += fn[u] * sw[u];
        atomicAdd(&acc[batch[n]], val * INV_LIN_OUT);
    }
    __syncthreads();
    if (t < N_GRAPHS && acc[t] != 0.f) atomicAdd(out + t, acc[t]);
}

// ---------------------------------------------------------------------------
extern "C" void kernel_launch(void* const* d_in, const int* in_sizes, int n_in,
                              void* d_out, int out_size)
{
    const float* x      = (const float*)d_in[0];
    const int*   row    = (const int*)  d_in[1];
    const int*   col    = (const int*)  d_in[2];
    const int*   batch  = (const int*)  d_in[3];
    const float* w_in0  = (const float*)d_in[4];
    const float* w_in1  = (const float*)d_in[5];
    const float* tpw    = (const float*)d_in[6];
    const float* w_out0 = (const float*)d_in[7];
    float* out = (float*)d_out;

    float *fa, *fb, *Fg;
    cudaGetSymbolAddress((void**)&fa, g_fa);
    cudaGetSymbolAddress((void**)&fb, g_fb);
    cudaGetSymbolAddress((void**)&Fg, g_F);

    cudaFuncSetAttribute(tp_gate_kernel,
                         cudaFuncAttributeMaxDynamicSharedMemorySize, SM_BYTES);

    proj_kernel<<<(N_NODES + 255) / 256, 256>>>(x, w_in0, w_in1, fa);

    float* cur = fa;
    float* nxt = fb;
    for (int l = 0; l < 3; ++l) {
        cudaMemsetAsync(Fg, 0, (size_t)N_NODES * 64 * sizeof(float));
        agg_kernel<<<(N_EDGES * 16 + 255) / 256, 256>>>(cur, row, col, Fg);
        tp_gate_kernel<<<592, 256, SM_BYTES>>>(cur, Fg, tpw + (size_t)l * 5 * 4096, nxt);
        float* tmp = cur; cur = nxt; nxt = tmp;
    }

    cudaMemsetAsync(out, 0, N_GRAPHS * sizeof(float));
    readout_kernel<<<(N_NODES + 255) / 256, 256>>>(cur, batch, w_out0, out);
}

// round 12
// speedup vs baseline: 1.1462x; 1.1462x over previous
#include <cuda_runtime.h>
#include <math.h>

#define N_NODES 50000
#define N_EDGES 600000
#define N_GRAPHS 64

static __device__ float g_fa[N_NODES * 64];
static __device__ float g_fb[N_NODES * 64];
static __device__ float g_F [N_NODES * 64];

#define INV_S3 0.57735026918962576f   /* 1/sqrt(3) */
#define INV_S2 0.70710678118654752f   /* 1/sqrt(2) */
#define NORM_S 0.044194173824159216f  /* 1/sqrt(512) */
#define NORM_V 0.036084391824351615f  /* 1/sqrt(768) */
#define INV_LIN_IN 0.35355339059327373f /* 1/sqrt(8) */
#define INV_LIN_OUT 0.25f

typedef unsigned long long u64;

// ---- packed fp32x2 helpers (sm_103a) --------------------------------------
__device__ __forceinline__ u64 pack2f(float a, float b) {
    u64 r;
    asm("mov.b64 %0, {%1, %2};" : "=l"(r) : "f"(a), "f"(b));
    return r;
}
__device__ __forceinline__ u64 ffma2(u64 a, u64 b, u64 c) {
    u64 d;
    asm("fma.rn.f32x2 %0, %1, %2, %3;" : "=l"(d) : "l"(a), "l"(b), "l"(c));
    return d;
}
__device__ __forceinline__ u64 addf2(u64 a, u64 b) {
    u64 d;
    asm("add.rn.f32x2 %0, %1, %2;" : "=l"(d) : "l"(a), "l"(b));
    return d;
}
__device__ __forceinline__ u64 neg2(u64 a) { return a ^ 0x8000000080000000ULL; }

// ---------------------------------------------------------------------------
// Input projection: x[N,32] -> f[N,64]  (s[16] | v[16][3] at 16+w*3+i)
// ---------------------------------------------------------------------------
__global__ __launch_bounds__(256) void proj_kernel(
    const float* __restrict__ x, const float* __restrict__ w0,
    const float* __restrict__ w1, float* __restrict__ f)
{
    __shared__ float sw0[128], sw1[128];
    int t = threadIdx.x;
    if (t < 128) sw0[t] = w0[t];
    else         sw1[t - 128] = w1[t - 128];
    __syncthreads();

    int n = blockIdx.x * 256 + t;
    if (n >= N_NODES) return;

    float xin[32];
    #pragma unroll
    for (int i = 0; i < 8; ++i)
        ((float4*)xin)[i] = ((const float4*)(x + n * 32))[i];

    float s[16];
    #pragma unroll
    for (int w = 0; w < 16; ++w) s[w] = 0.f;
    #pragma unroll
    for (int u = 0; u < 8; ++u) {
        float xu = xin[u];
        #pragma unroll
        for (int w = 0; w < 16; ++w) s[w] += xu * sw0[u * 16 + w];
    }
    float vv[48];
    #pragma unroll
    for (int q = 0; q < 48; ++q) vv[q] = 0.f;
    #pragma unroll
    for (int u = 0; u < 8; ++u) {
        float x0 = xin[8 + u * 3 + 0];
        float x1 = xin[8 + u * 3 + 1];
        float x2 = xin[8 + u * 3 + 2];
        #pragma unroll
        for (int w = 0; w < 16; ++w) {
            float wt = sw1[u * 16 + w];
            vv[w * 3 + 0] += x0 * wt;
            vv[w * 3 + 1] += x1 * wt;
            vv[w * 3 + 2] += x2 * wt;
        }
    }
    float* fn = f + n * 64;
    #pragma unroll
    for (int w = 0; w < 16; ++w) fn[w] = s[w] * INV_LIN_IN;
    #pragma unroll
    for (int q = 0; q < 48; ++q) fn[16 + q] = vv[q] * INV_LIN_IN;
}

// ---------------------------------------------------------------------------
// Aggregation: F[row[e]] += f[col[e]] via red.global.v4.f32.add (REDG.128)
// ---------------------------------------------------------------------------
__global__ __launch_bounds__(256) void agg_kernel(
    const float* __restrict__ f, const int* __restrict__ row,
    const int* __restrict__ col, float* __restrict__ F)
{
    unsigned idx = blockIdx.x * 256u + threadIdx.x;
    unsigned e = idx >> 4, q = idx & 15u;
    if (e >= N_EDGES) return;
    int c = __ldg(col + e);
    int r = __ldg(row + e);
    float4 val = ((const float4*)(f + (size_t)c * 64))[q];
    float* dst = F + (size_t)r * 64 + q * 4;
    asm volatile("red.global.v4.f32.add [%0], {%1, %2, %3, %4};"
                 :: "l"(dst), "f"(val.x), "f"(val.y), "f"(val.z), "f"(val.w)
                 : "memory");
}

// ---------------------------------------------------------------------------
// Per-node TP + gate, node-pair f32x2 packed, PATH-SPECIALIZED warp groups.
// Block = 512 threads = 2 groups x 256. Thread t8 = v*16 + w.
//   G0 (tid<256):  paths 0,1 weights in regs, path 3 weights from smem
//   G1 (tid>=256): paths 2,4 weights in regs
// 4 nodes (2 f32x2 pairs) per block iteration; stage 2 runs both pairs
// concurrently across the 512 threads.
// ---------------------------------------------------------------------------
// shared memory layout (u64 units)
#define SM_W3    0                       /* u64[16][256]        = 4096 */
#define SM_SFP   4096                    /* u64[2][128]         = 256  */
#define SM_TSP   (4096 + 256)            /* u64[2][11][256]     = 5632 */
#define SM_OUTB  (4096 + 256 + 5632)     /* u64[2][64]          = 128  */
#define SM_U64S  (4096 + 256 + 5632 + 128)
#define SM_BYTES (SM_U64S * 8)

__global__ __launch_bounds__(512, 1) void tp_gate_kernel(
    const float* __restrict__ f, const float* __restrict__ Fg,
    const float* __restrict__ W, float* __restrict__ fout)
{
    extern __shared__ u64 dsm[];
    u64* wsm3 = dsm + SM_W3;
    u64* sfp  = dsm + SM_SFP;
    u64* tsp  = dsm + SM_TSP;
    u64* outb = dsm + SM_OUTB;

    const int tid = threadIdx.x;
    const int gid = tid >> 8;     // group 0/1
    const int t8  = tid & 255;    // t8 = v*16 + w

    // ---- weight preload ----
    // G0: wA=path0, wB=path1 (scalar paths); G1: wA=path2, wB=path4
    const int pA = (gid == 0) ? 0 : 2;
    const int pB = (gid == 0) ? 1 : 4;
    u64 wAr[16], wBr[16];
    #pragma unroll
    for (int u = 0; u < 16; ++u) {
        float a = __ldg(W + pA * 4096 + u * 256 + t8);
        float b = __ldg(W + pB * 4096 + u * 256 + t8);
        wAr[u] = pack2f(a, a);
        wBr[u] = pack2f(b, b);
    }
    // path 3 weights -> smem (duplicated u64), loaded by whole block
    for (int idx = tid; idx < 16 * 256; idx += 512) {
        float a = __ldg(W + 3 * 4096 + idx);
        wsm3[idx] = pack2f(a, a);
    }
    __syncthreads();

    const u64 INV3p = pack2f(INV_S3, INV_S3);
    const u64 INV2p = pack2f(INV_S2, INV_S2);

    for (int base = blockIdx.x * 4; base < N_NODES; base += gridDim.x * 4) {

        // ---- feature load: 512 floats, one per thread ----
        // slot tid = p*256 + c*2 + s ; node = base + p*2 + s
        {
            int p = tid >> 8;
            int c = (tid & 255) >> 1;
            int s = tid & 1;
            int node = base + p * 2 + s;
            float val = (c < 64) ? f[(size_t)node * 64 + c]
                                 : Fg[(size_t)node * 64 + (c - 64)];
            ((float*)sfp)[tid] = val;
        }
        __syncthreads();

        // ---- stage 1: left contractions, paths split across groups ----
        #pragma unroll
        for (int p = 0; p < 2; ++p) {
            const u64* fp = sfp + p * 128;
            u64* tp = tsp + p * (11 * 256);
            if (gid == 0) {
                u64 a0 = 0, a1 = 0, a3x = 0, a3y = 0, a3z = 0;
                #pragma unroll
                for (int u = 0; u < 16; ++u) {
                    u64 su = fp[u];
                    u64 vx = fp[16 + u * 3 + 0];
                    u64 vy = fp[16 + u * 3 + 1];
                    u64 vz = fp[16 + u * 3 + 2];
                    u64 w3 = wsm3[u * 256 + t8];
                    a0  = ffma2(su, wAr[u], a0);
                    a1  = ffma2(su, wBr[u], a1);
                    a3x = ffma2(vx, w3, a3x);
                    a3y = ffma2(vy, w3, a3y);
                    a3z = ffma2(vz, w3, a3z);
                }
                tp[0 * 256 + t8] = a0;
                tp[1 * 256 + t8] = a1;
                tp[5 * 256 + t8] = a3x;
                tp[6 * 256 + t8] = a3y;
                tp[7 * 256 + t8] = a3z;
            } else {
                u64 a2x = 0, a2y = 0, a2z = 0;
                u64 a4x = 0, a4y = 0, a4z = 0;
                #pragma unroll
                for (int u = 0; u < 16; ++u) {
                    u64 vx = fp[16 + u * 3 + 0];
                    u64 vy = fp[16 + u * 3 + 1];
                    u64 vz = fp[16 + u * 3 + 2];
                    a2x = ffma2(vx, wAr[u], a2x);
                    a2y = ffma2(vy, wAr[u], a2y);
                    a2z = ffma2(vz, wAr[u], a2z);
                    a4x = ffma2(vx, wBr[u], a4x);
                    a4y = ffma2(vy, wBr[u], a4y);
                    a4z = ffma2(vz, wBr[u], a4z);
                }
                tp[2 * 256 + t8] = a2x;
                tp[3 * 256 + t8] = a2y;
                tp[4 * 256 + t8] = a2z;
                tp[8 * 256 + t8] = a4x;
                tp[9 * 256 + t8] = a4y;
                tp[10 * 256 + t8] = a4z;
            }
        }
        __syncthreads();

        // ---- stage 2: both pairs concurrently; 4 threads per output ----
        {
            const int p = tid >> 8;
            const int o = t8 >> 2, q = t8 & 3;
            const u64* SD = sfp + p * 128 + 64;
            const u64* VD = sfp + p * 128 + 80;
            const u64* tp = tsp + p * (11 * 256);
            u64 acc = 0;
            if (o < 16) {
                const int w = o;
                u64 accd = 0;
                #pragma unroll
                for (int dv = 0; dv < 4; ++dv) {
                    int v = q * 4 + dv;
                    int ti = v * 16 + w;
                    acc  = ffma2(tp[0 * 256 + ti], SD[v], acc);
                    accd = ffma2(tp[5 * 256 + ti], VD[v * 3 + 0], accd);
                    accd = ffma2(tp[6 * 256 + ti], VD[v * 3 + 1], accd);
                    accd = ffma2(tp[7 * 256 + ti], VD[v * 3 + 2], accd);
                }
                acc = ffma2(accd, INV3p, acc);
            } else {
                const int q2 = o - 16;
                const int w = q2 / 3, k = q2 % 3;
                const int i = (k + 1) % 3, j = (k + 2) % 3;
                u64 acc5 = 0;
                #pragma unroll
                for (int dv = 0; dv < 4; ++dv) {
                    int v = q * 4 + dv;
                    int ti = v * 16 + w;
                    acc  = ffma2(tp[1 * 256 + ti], VD[v * 3 + k], acc);
                    acc  = ffma2(tp[(2 + k) * 256 + ti], SD[v], acc);
                    acc5 = ffma2(tp[(8 + i) * 256 + ti], VD[v * 3 + j], acc5);
                    acc5 = ffma2(neg2(tp[(8 + j) * 256 + ti]), VD[v * 3 + i], acc5);
                }
                acc = ffma2(acc5, INV2p, acc);
            }
            acc = addf2(acc, __shfl_xor_sync(0xffffffffu, acc, 1));
            acc = addf2(acc, __shfl_xor_sync(0xffffffffu, acc, 2));
            if (q == 0) outb[p * 64 + o] = acc;
        }
        __syncthreads();

        // ---- gate + writeback: 4 nodes x 64 outputs = 256 threads ----
        if (tid < 256) {
            const int nn = tid >> 6;          // node within group (0..3)
            const int p = nn >> 1, s = nn & 1;
            const int oo = tid & 63;
            const float* obF = (const float*)outb;
            float raw = obF[(p * 64 + oo) * 2 + s];
            float r;
            if (oo < 16) {
                float sp = NORM_S * raw;
                float sg = 1.f / (1.f + expf(-sp));
                r = sp * sg;
            } else {
                int w = (oo - 16) / 3;
                float sp = NORM_S * obF[(p * 64 + w) * 2 + s];
                float sg = 1.f / (1.f + expf(-sp));
                r = NORM_V * raw * sg;
            }
            fout[(size_t)(base + nn) * 64 + oo] = r;
        }
        __syncthreads();
    }
}

// ---------------------------------------------------------------------------
// Readout: energy[g] = sum_n (s[n]·w_out) * 0.25   grouped by batch_idx
// ---------------------------------------------------------------------------
__global__ __launch_bounds__(256) void readout_kernel(
    const float* __restrict__ f, const int* __restrict__ batch,
    const float* __restrict__ w, float* __restrict__ out)
{
    __shared__ float acc[N_GRAPHS];
    __shared__ float sw[16];
    int t = threadIdx.x;
    if (t < N_GRAPHS) acc[t] = 0.f;
    if (t < 16) sw[t] = w[t];
    __syncthreads();
    int n = blockIdx.x * 256 + t;
    if (n < N_NODES) {
        const float* fn = f + (size_t)n * 64;
        float val = 0.f;
        #pragma unroll
        for (int u = 0; u < 16; ++u) val += fn[u] * sw[u];
        atomicAdd(&acc[batch[n]], val * INV_LIN_OUT);
    }
    __syncthreads();
    if (t < N_GRAPHS && acc[t] != 0.f) atomicAdd(out + t, acc[t]);
}

// ---------------------------------------------------------------------------
extern "C" void kernel_launch(void* const* d_in, const int* in_sizes, int n_in,
                              void* d_out, int out_size)
{
    const float* x      = (const float*)d_in[0];
    const int*   row    = (const int*)  d_in[1];
    const int*   col    = (const int*)  d_in[2];
    const int*   batch  = (const int*)  d_in[3];
    const float* w_in0  = (const float*)d_in[4];
    const float* w_in1  = (const float*)d_in[5];
    const float* tpw    = (const float*)d_in[6];
    const float* w_out0 = (const float*)d_in[7];
    float* out = (float*)d_out;

    float *fa, *fb, *Fg;
    cudaGetSymbolAddress((void**)&fa, g_fa);
    cudaGetSymbolAddress((void**)&fb, g_fb);
    cudaGetSymbolAddress((void**)&Fg, g_F);

    cudaFuncSetAttribute(tp_gate_kernel,
                         cudaFuncAttributeMaxDynamicSharedMemorySize, SM_BYTES);

    proj_kernel<<<(N_NODES + 255) / 256, 256>>>(x, w_in0, w_in1, fa);

    float* cur = fa;
    float* nxt = fb;
    for (int l = 0; l < 3; ++l) {
        cudaMemsetAsync(Fg, 0, (size_t)N_NODES * 64 * sizeof(float));
        agg_kernel<<<(N_EDGES * 16 + 255) / 256, 256>>>(cur, row, col, Fg);
        tp_gate_kernel<<<592, 512, SM_BYTES>>>(cur, Fg, tpw + (size_t)l * 5 * 4096, nxt);
        float* tmp = cur; cur = nxt; nxt = tmp;
    }

    cudaMemsetAsync(out, 0, N_GRAPHS * sizeof(float));
    readout_kernel<<<(N_NODES + 255) / 256, 256>>>(cur, batch, w_out0, out);
}

// round 14
// speedup vs baseline: 1.6554x; 1.4443x over previous
#include <cuda_runtime.h>
#include <math.h>

#define N_NODES 50000
#define N_EDGES 600000
#define N_GRAPHS 64

static __device__ float g_fa[N_NODES * 64];
static __device__ float g_fb[N_NODES * 64];
static __device__ float g_F [N_NODES * 64];

#define INV_S3 0.57735026918962576f   /* 1/sqrt(3) */
#define INV_S2 0.70710678118654752f   /* 1/sqrt(2) */
#define NORM_S 0.044194173824159216f  /* 1/sqrt(512) */
#define NORM_V 0.036084391824351615f  /* 1/sqrt(768) */
#define INV_LIN_IN 0.35355339059327373f /* 1/sqrt(8) */
#define INV_LIN_OUT 0.25f

typedef unsigned long long u64;

// ---- packed fp32x2 helpers (sm_103a) --------------------------------------
__device__ __forceinline__ u64 pack2f(float a, float b) {
    u64 r;
    asm("mov.b64 %0, {%1, %2};" : "=l"(r) : "f"(a), "f"(b));
    return r;
}
__device__ __forceinline__ void unpack2f(float& a, float& b, u64 p) {
    asm("mov.b64 {%0, %1}, %2;" : "=f"(a), "=f"(b) : "l"(p));
}
__device__ __forceinline__ u64 ffma2(u64 a, u64 b, u64 c) {
    u64 d;
    asm("fma.rn.f32x2 %0, %1, %2, %3;" : "=l"(d) : "l"(a), "l"(b), "l"(c));
    return d;
}
__device__ __forceinline__ u64 addf2(u64 a, u64 b) {
    u64 d;
    asm("add.rn.f32x2 %0, %1, %2;" : "=l"(d) : "l"(a), "l"(b));
    return d;
}
__device__ __forceinline__ u64 neg2(u64 a) { return a ^ 0x8000000080000000ULL; }

// ---------------------------------------------------------------------------
// Input projection: x[N,32] -> f[N,64]  (s[16] | v[16][3] at 16+w*3+i)
// ---------------------------------------------------------------------------
__global__ __launch_bounds__(256) void proj_kernel(
    const float* __restrict__ x, const float* __restrict__ w0,
    const float* __restrict__ w1, float* __restrict__ f)
{
    __shared__ float sw0[128], sw1[128];
    int t = threadIdx.x;
    if (t < 128) sw0[t] = w0[t];
    else         sw1[t - 128] = w1[t - 128];
    __syncthreads();

    int n = blockIdx.x * 256 + t;
    if (n >= N_NODES) return;

    float xin[32];
    #pragma unroll
    for (int i = 0; i < 8; ++i)
        ((float4*)xin)[i] = ((const float4*)(x + n * 32))[i];

    float s[16];
    #pragma unroll
    for (int w = 0; w < 16; ++w) s[w] = 0.f;
    #pragma unroll
    for (int u = 0; u < 8; ++u) {
        float xu = xin[u];
        #pragma unroll
        for (int w = 0; w < 16; ++w) s[w] += xu * sw0[u * 16 + w];
    }
    float vv[48];
    #pragma unroll
    for (int q = 0; q < 48; ++q) vv[q] = 0.f;
    #pragma unroll
    for (int u = 0; u < 8; ++u) {
        float x0 = xin[8 + u * 3 + 0];
        float x1 = xin[8 + u * 3 + 1];
        float x2 = xin[8 + u * 3 + 2];
        #pragma unroll
        for (int w = 0; w < 16; ++w) {
            float wt = sw1[u * 16 + w];
            vv[w * 3 + 0] += x0 * wt;
            vv[w * 3 + 1] += x1 * wt;
            vv[w * 3 + 2] += x2 * wt;
        }
    }
    float* fn = f + n * 64;
    #pragma unroll
    for (int w = 0; w < 16; ++w) fn[w] = s[w] * INV_LIN_IN;
    #pragma unroll
    for (int q = 0; q < 48; ++q) fn[16 + q] = vv[q] * INV_LIN_IN;
}

// ---------------------------------------------------------------------------
// Aggregation: F[row[e]] += f[col[e]] via red.global.v4.f32.add (REDG.128)
// ---------------------------------------------------------------------------
__global__ __launch_bounds__(256) void agg_kernel(
    const float* __restrict__ f, const int* __restrict__ row,
    const int* __restrict__ col, float* __restrict__ F)
{
    unsigned idx = blockIdx.x * 256u + threadIdx.x;
    unsigned e = idx >> 4, q = idx & 15u;
    if (e >= N_EDGES) return;
    int c = __ldg(col + e);
    int r = __ldg(row + e);
    float4 val = ((const float4*)(f + (size_t)c * 64))[q];
    float* dst = F + (size_t)r * 64 + q * 4;
    asm volatile("red.global.v4.f32.add [%0], {%1, %2, %3, %4};"
                 :: "l"(dst), "f"(val.x), "f"(val.y), "f"(val.z), "f"(val.w)
                 : "memory");
}

// ---------------------------------------------------------------------------
// Per-node TP + gate, (v,w)-pair f32x2 packed with u-SPLIT lane pairs.
// Thread t8 = slot*2 + uh, slot = v*8 + wp covers outputs (v, 2wp),(v, 2wp+1);
// uh selects u in [0,8) or [8,16). All 5 paths' weights live in registers
// (5 paths x 8 u = 40 u64 = 80 regs). Stage-1 partials combine via one
// shfl_xor(1) per path. 256 threads, 2 blocks/SM -> 16 warps with zero smem
// weight traffic. 2 nodes per iteration; stage 2 runs both concurrently.
// tsp rows padded to stride 9 u64 to break v*8 bank aliasing.
// ---------------------------------------------------------------------------
#define TSP_STRIDE 144   /* 16 * 9 */

__global__ __launch_bounds__(256, 2) void tp_gate_kernel(
    const float* __restrict__ f, const float* __restrict__ Fg,
    const float* __restrict__ W, float* __restrict__ fout)
{
    __shared__ u64 sfd[2][128];               //  2 KB duplicated features
    __shared__ u64 tsp[2][11][TSP_STRIDE];    // 25.3 KB contractions (padded)
    __shared__ float outb[2][64];             //  0.5 KB raw TP outputs

    const int t8   = threadIdx.x;
    const int slot = t8 >> 1;        // v*8 + wp
    const int uh   = t8 & 1;         // u half
    const int v    = slot >> 3;
    const int wp   = slot & 7;
    const int sl   = v * 9 + wp;     // padded tsp slot

    // ---- weight preload: 5 paths x 8 u, packed (w=2wp, 2wp+1) ----
    const float2* Wf2 = (const float2*)W;
    u64 wr[5][8];
    #pragma unroll
    for (int p = 0; p < 5; ++p)
        #pragma unroll
        for (int j = 0; j < 8; ++j) {
            float2 a = __ldg(Wf2 + p * 2048 + (uh * 8 + j) * 128 + slot);
            wr[p][j] = pack2f(a.x, a.y);
        }

    const u64 INV3p = pack2f(INV_S3, INV_S3);
    const u64 INV2p = pack2f(INV_S2, INV_S2);

    for (int base = blockIdx.x * 2; base < N_NODES; base += gridDim.x * 2) {

        // ---- feature load: 2 nodes x 128 comps, duplicate-packed ----
        {
            int k = t8 >> 7, c = t8 & 127;
            int node = base + k;
            float val = (c < 64) ? f[(size_t)node * 64 + c]
                                 : Fg[(size_t)node * 64 + (c - 64)];
            sfd[k][c] = pack2f(val, val);
        }
        __syncthreads();

        // ---- stage 1: 11 left contractions, u-split + shfl combine ----
        #pragma unroll
        for (int k = 0; k < 2; ++k) {
            const u64* fp = sfd[k];
            u64 a0 = 0, a1 = 0;
            u64 a2x = 0, a2y = 0, a2z = 0;
            u64 a3x = 0, a3y = 0, a3z = 0;
            u64 a4x = 0, a4y = 0, a4z = 0;
            #pragma unroll
            for (int j = 0; j < 8; ++j) {
                int u = uh * 8 + j;
                u64 su = fp[u];
                u64 vx = fp[16 + u * 3 + 0];
                u64 vy = fp[16 + u * 3 + 1];
                u64 vz = fp[16 + u * 3 + 2];
                a0  = ffma2(su, wr[0][j], a0);
                a1  = ffma2(su, wr[1][j], a1);
                a2x = ffma2(vx, wr[2][j], a2x);
                a2y = ffma2(vy, wr[2][j], a2y);
                a2z = ffma2(vz, wr[2][j], a2z);
                a3x = ffma2(vx, wr[3][j], a3x);
                a3y = ffma2(vy, wr[3][j], a3y);
                a3z = ffma2(vz, wr[3][j], a3z);
                a4x = ffma2(vx, wr[4][j], a4x);
                a4y = ffma2(vy, wr[4][j], a4y);
                a4z = ffma2(vz, wr[4][j], a4z);
            }
            a0  = addf2(a0,  __shfl_xor_sync(0xffffffffu, a0,  1));
            a1  = addf2(a1,  __shfl_xor_sync(0xffffffffu, a1,  1));
            a2x = addf2(a2x, __shfl_xor_sync(0xffffffffu, a2x, 1));
            a2y = addf2(a2y, __shfl_xor_sync(0xffffffffu, a2y, 1));
            a2z = addf2(a2z, __shfl_xor_sync(0xffffffffu, a2z, 1));
            a3x = addf2(a3x, __shfl_xor_sync(0xffffffffu, a3x, 1));
            a3y = addf2(a3y, __shfl_xor_sync(0xffffffffu, a3y, 1));
            a3z = addf2(a3z, __shfl_xor_sync(0xffffffffu, a3z, 1));
            a4x = addf2(a4x, __shfl_xor_sync(0xffffffffu, a4x, 1));
            a4y = addf2(a4y, __shfl_xor_sync(0xffffffffu, a4y, 1));
            a4z = addf2(a4z, __shfl_xor_sync(0xffffffffu, a4z, 1));
            if (uh == 0) {
                tsp[k][0][sl] = a0;  tsp[k][1][sl] = a1;
                tsp[k][2][sl] = a2x; tsp[k][3][sl] = a2y; tsp[k][4][sl] = a2z;
                tsp[k][5][sl] = a3x; tsp[k][6][sl] = a3y; tsp[k][7][sl] = a3z;
                tsp[k][8][sl] = a4x; tsp[k][9][sl] = a4y; tsp[k][10][sl] = a4z;
            }
        }
        __syncthreads();

        // ---- stage 2: both nodes concurrently; 4 threads per output-pair ----
        {
            const int p  = t8 >> 7;          // node
            const int t7 = t8 & 127;
            const int op = t7 >> 2, q = t7 & 3;
            const u64* SD = sfd[p] + 64;
            const u64* VD = sfd[p] + 80;
            const u64 (*tp)[TSP_STRIDE] = tsp[p];
            u64 acc = 0;
            if (op < 8) {
                const int wp2 = op;
                u64 accd = 0;
                #pragma unroll
                for (int dv = 0; dv < 4; ++dv) {
                    int vv = q * 4 + dv;
                    int ti = vv * 9 + wp2;
                    acc  = ffma2(tp[0][ti], SD[vv], acc);
                    accd = ffma2(tp[5][ti], VD[vv * 3 + 0], accd);
                    accd = ffma2(tp[6][ti], VD[vv * 3 + 1], accd);
                    accd = ffma2(tp[7][ti], VD[vv * 3 + 2], accd);
                }
                acc = ffma2(accd, INV3p, acc);
            } else {
                const int vo = op - 8;
                const int wp2 = vo / 3, kk = vo % 3;
                const int i = (kk + 1) % 3, j = (kk + 2) % 3;
                u64 acc5 = 0;
                #pragma unroll
                for (int dv = 0; dv < 4; ++dv) {
                    int vv = q * 4 + dv;
                    int ti = vv * 9 + wp2;
                    acc  = ffma2(tp[1][ti], VD[vv * 3 + kk], acc);
                    acc  = ffma2(tp[2 + kk][ti], SD[vv], acc);
                    acc5 = ffma2(tp[8 + i][ti], VD[vv * 3 + j], acc5);
                    acc5 = ffma2(neg2(tp[8 + j][ti]), VD[vv * 3 + i], acc5);
                }
                acc = ffma2(acc5, INV2p, acc);
            }
            acc = addf2(acc, __shfl_xor_sync(0xffffffffu, acc, 1));
            acc = addf2(acc, __shfl_xor_sync(0xffffffffu, acc, 2));
            if (q == 0) {
                float lo, hi;
                unpack2f(lo, hi, acc);
                if (op < 8) {
                    outb[p][2 * op]     = lo;
                    outb[p][2 * op + 1] = hi;
                } else {
                    const int vo = op - 8;
                    const int wp2 = vo / 3, kk = vo % 3;
                    outb[p][16 + (2 * wp2) * 3 + kk]     = lo;
                    outb[p][16 + (2 * wp2 + 1) * 3 + kk] = hi;
                }
            }
        }
        __syncthreads();

        // ---- gate + writeback: 2 nodes x 64 outputs = 128 threads ----
        if (t8 < 128) {
            const int k = t8 >> 6, oo = t8 & 63;
            float raw = outb[k][oo];
            float r;
            if (oo < 16) {
                float sp = NORM_S * raw;
                float sg = 1.f / (1.f + expf(-sp));
                r = sp * sg;
            } else {
                int w = (oo - 16) / 3;
                float sp = NORM_S * outb[k][w];
                float sg = 1.f / (1.f + expf(-sp));
                r = NORM_V * raw * sg;
            }
            fout[(size_t)(base + k) * 64 + oo] = r;
        }
        __syncthreads();
    }
}

// ---------------------------------------------------------------------------
// Readout: energy[g] = sum_n (s[n]·w_out) * 0.25   grouped by batch_idx
// ---------------------------------------------------------------------------
__global__ __launch_bounds__(256) void readout_kernel(
    const float* __restrict__ f, const int* __restrict__ batch,
    const float* __restrict__ w, float* __restrict__ out)
{
    __shared__ float acc[N_GRAPHS];
    __shared__ float sw[16];
    int t = threadIdx.x;
    if (t < N_GRAPHS) acc[t] = 0.f;
    if (t < 16) sw[t] = w[t];
    __syncthreads();
    int n = blockIdx.x * 256 + t;
    if (n < N_NODES) {
        const float* fn = f + (size_t)n * 64;
        float val = 0.f;
        #pragma unroll
        for (int u = 0; u < 16; ++u) val += fn[u] * sw[u];
        atomicAdd(&acc[batch[n]], val * INV_LIN_OUT);
    }
    __syncthreads();
    if (t < N_GRAPHS && acc[t] != 0.f) atomicAdd(out + t, acc[t]);
}

// ---------------------------------------------------------------------------
extern "C" void kernel_launch(void* const* d_in, const int* in_sizes, int n_in,
                              void* d_out, int out_size)
{
    const float* x      = (const float*)d_in[0];
    const int*   row    = (const int*)  d_in[1];
    const int*   col    = (const int*)  d_in[2];
    const int*   batch  = (const int*)  d_in[3];
    const float* w_in0  = (const float*)d_in[4];
    const float* w_in1  = (const float*)d_in[5];
    const float* tpw    = (const float*)d_in[6];
    const float* w_out0 = (const float*)d_in[7];
    float* out = (float*)d_out;

    float *fa, *fb, *Fg;
    cudaGetSymbolAddress((void**)&fa, g_fa);
    cudaGetSymbolAddress((void**)&fb, g_fb);
    cudaGetSymbolAddress((void**)&Fg, g_F);

    proj_kernel<<<(N_NODES + 255) / 256, 256>>>(x, w_in0, w_in1, fa);

    float* cur = fa;
    float* nxt = fb;
    for (int l = 0; l < 3; ++l) {
        cudaMemsetAsync(Fg, 0, (size_t)N_NODES * 64 * sizeof(float));
        agg_kernel<<<(N_EDGES * 16 + 255) / 256, 256>>>(cur, row, col, Fg);
        tp_gate_kernel<<<296, 256>>>(cur, Fg, tpw + (size_t)l * 5 * 4096, nxt);
        float* tmp = cur; cur = nxt; nxt = tmp;
    }

    cudaMemsetAsync(out, 0, N_GRAPHS * sizeof(float));
    readout_kernel<<<(N_NODES + 255) / 256, 256>>>(cur, batch, w_out0, out);
}

// round 16
// speedup vs baseline: 1.7787x; 1.0745x over previous
#include <cuda_runtime.h>
#include <math.h>

#define N_NODES 50000
#define N_EDGES 600000
#define N_GRAPHS 64

static __device__ float g_fa[N_NODES * 64];
static __device__ float g_fb[N_NODES * 64];
static __device__ float g_F [N_NODES * 64];   // zero-init at load; kernel re-zeroes after use

#define INV_S3 0.57735026918962576f   /* 1/sqrt(3) */
#define INV_S2 0.70710678118654752f   /* 1/sqrt(2) */
#define NORM_S 0.044194173824159216f  /* 1/sqrt(512) */
#define NORM_V 0.036084391824351615f  /* 1/sqrt(768) */
#define INV_LIN_IN 0.35355339059327373f /* 1/sqrt(8) */
#define INV_LIN_OUT 0.25f

typedef unsigned long long u64;

// ---- packed fp32x2 helpers (sm_103a) --------------------------------------
__device__ __forceinline__ u64 pack2f(float a, float b) {
    u64 r;
    asm("mov.b64 %0, {%1, %2};" : "=l"(r) : "f"(a), "f"(b));
    return r;
}
__device__ __forceinline__ void unpack2f(float& a, float& b, u64 p) {
    asm("mov.b64 {%0, %1}, %2;" : "=f"(a), "=f"(b) : "l"(p));
}
__device__ __forceinline__ u64 ffma2(u64 a, u64 b, u64 c) {
    u64 d;
    asm("fma.rn.f32x2 %0, %1, %2, %3;" : "=l"(d) : "l"(a), "l"(b), "l"(c));
    return d;
}
__device__ __forceinline__ u64 addf2(u64 a, u64 b) {
    u64 d;
    asm("add.rn.f32x2 %0, %1, %2;" : "=l"(d) : "l"(a), "l"(b));
    return d;
}
__device__ __forceinline__ u64 neg2(u64 a) { return a ^ 0x8000000080000000ULL; }

// ---------------------------------------------------------------------------
// Input projection: x[N,32] -> f[N,64]  (s[16] | v[16][3] at 16+w*3+i)
// ---------------------------------------------------------------------------
__global__ __launch_bounds__(256) void proj_kernel(
    const float* __restrict__ x, const float* __restrict__ w0,
    const float* __restrict__ w1, float* __restrict__ f)
{
    __shared__ float sw0[128], sw1[128];
    int t = threadIdx.x;
    if (t < 128) sw0[t] = w0[t];
    else         sw1[t - 128] = w1[t - 128];
    __syncthreads();

    int n = blockIdx.x * 256 + t;
    if (n >= N_NODES) return;

    float xin[32];
    #pragma unroll
    for (int i = 0; i < 8; ++i)
        ((float4*)xin)[i] = ((const float4*)(x + n * 32))[i];

    float s[16];
    #pragma unroll
    for (int w = 0; w < 16; ++w) s[w] = 0.f;
    #pragma unroll
    for (int u = 0; u < 8; ++u) {
        float xu = xin[u];
        #pragma unroll
        for (int w = 0; w < 16; ++w) s[w] += xu * sw0[u * 16 + w];
    }
    float vv[48];
    #pragma unroll
    for (int q = 0; q < 48; ++q) vv[q] = 0.f;
    #pragma unroll
    for (int u = 0; u < 8; ++u) {
        float x0 = xin[8 + u * 3 + 0];
        float x1 = xin[8 + u * 3 + 1];
        float x2 = xin[8 + u * 3 + 2];
        #pragma unroll
        for (int w = 0; w < 16; ++w) {
            float wt = sw1[u * 16 + w];
            vv[w * 3 + 0] += x0 * wt;
            vv[w * 3 + 1] += x1 * wt;
            vv[w * 3 + 2] += x2 * wt;
        }
    }
    float* fn = f + n * 64;
    #pragma unroll
    for (int w = 0; w < 16; ++w) fn[w] = s[w] * INV_LIN_IN;
    #pragma unroll
    for (int q = 0; q < 48; ++q) fn[16 + q] = vv[q] * INV_LIN_IN;
}

// ---------------------------------------------------------------------------
// Aggregation: F[row[e]] += f[col[e]] via red.global.v4.f32.add (REDG.128)
// ---------------------------------------------------------------------------
__global__ __launch_bounds__(256) void agg_kernel(
    const float* __restrict__ f, const int* __restrict__ row,
    const int* __restrict__ col, float* __restrict__ F)
{
    unsigned idx = blockIdx.x * 256u + threadIdx.x;
    unsigned e = idx >> 4, q = idx & 15u;
    if (e >= N_EDGES) return;
    int c = __ldg(col + e);
    int r = __ldg(row + e);
    float4 val = ((const float4*)(f + (size_t)c * 64))[q];
    float* dst = F + (size_t)r * 64 + q * 4;
    asm volatile("red.global.v4.f32.add [%0], {%1, %2, %3, %4};"
                 :: "l"(dst), "f"(val.x), "f"(val.y), "f"(val.z), "f"(val.w)
                 : "memory");
}

// ---------------------------------------------------------------------------
// Per-node TP + gate: (v,w)-pair f32x2 packing with u-split lane pairs,
// NPB=4 nodes/iteration, double-buffered feature prefetch, Fg self-zeroing.
// Thread t8 = slot*2 + uh, slot = v*8 + wp; all 5 weight paths in registers
// (40 u64). Stage-1 partials combine via shfl_xor(1).
//
// Shared memory map (u64 units, sizes written out):
//   sfd : u64[2][NPB][128]      = 2*4*128      = 1024
//   tsp : u64[NPB][11][TSTR]    = 4*11*144     = 6336
//   outb: float[NPB][64]        = 256 floats   =  128 u64   <-- R15 bug was 32
// ---------------------------------------------------------------------------
#define NPB 4
#define TSTR 144   /* 16 * 9, padded stride */

#define SMU_SFD  0
#define SMU_TSP  (SMU_SFD + 2 * NPB * 128)            /* 1024 */
#define SMU_OUT  (SMU_TSP + NPB * 11 * TSTR)          /* 1024 + 6336 */
#define SMU_TOT  (SMU_OUT + (NPB * 64 * 4 + 7) / 8)   /* + 128 u64 */
#define SM_BYTES (SMU_TOT * 8)

__global__ __launch_bounds__(256, 2) void tp_gate_kernel(
    const float* __restrict__ f, float* __restrict__ Fg,
    const float* __restrict__ W, float* __restrict__ fout)
{
    extern __shared__ u64 dsm[];
    u64 (*sfd)[NPB][128] = (u64 (*)[NPB][128])(dsm + SMU_SFD);
    u64 (*tsp)[11][TSTR] = (u64 (*)[11][TSTR])(dsm + SMU_TSP);
    float* outb          = (float*)(dsm + SMU_OUT);

    const int t8   = threadIdx.x;
    const int slot = t8 >> 1;        // v*8 + wp
    const int uh   = t8 & 1;         // u half
    const int v    = slot >> 3;
    const int wp   = slot & 7;
    const int sl   = v * 9 + wp;     // padded tsp slot

    // ---- weight preload: 5 paths x 8 u, packed (w=2wp, 2wp+1) ----
    const float2* Wf2 = (const float2*)W;
    u64 wr[5][8];
    #pragma unroll
    for (int p = 0; p < 5; ++p)
        #pragma unroll
        for (int j = 0; j < 8; ++j) {
            float2 a = __ldg(Wf2 + p * 2048 + (uh * 8 + j) * 128 + slot);
            wr[p][j] = pack2f(a.x, a.y);
        }

    const u64 INV3p = pack2f(INV_S3, INV_S3);
    const u64 INV2p = pack2f(INV_S2, INV_S2);
    const int stride = gridDim.x * NPB;

    // ---- initial feature load (+ Fg zeroing) into buffer 0 ----
    int base = blockIdx.x * NPB;
    {
        #pragma unroll
        for (int k = 0; k < 2; ++k) {
            int idx = k * 256 + t8;
            int nn = idx >> 7, c = idx & 127;
            int node = base + nn;
            float val = 0.f;
            if (node < N_NODES) {
                if (c < 64) val = f[(size_t)node * 64 + c];
                else {
                    val = Fg[(size_t)node * 64 + (c - 64)];
                    Fg[(size_t)node * 64 + (c - 64)] = 0.f;
                }
            }
            sfd[0][nn][c] = pack2f(val, val);
        }
    }
    __syncthreads();

    int buf = 0;
    for (; base < N_NODES; base += stride, buf ^= 1) {
        const int nbase = base + stride;

        // ---- prefetch next iteration's features (LDG only) ----
        float pf0 = 0.f, pf1 = 0.f;
        {
            int idx0 = t8, idx1 = 256 + t8;
            int n0 = nbase + (idx0 >> 7), c0 = idx0 & 127;
            int n1 = nbase + (idx1 >> 7), c1 = idx1 & 127;
            if (n0 < N_NODES)
                pf0 = (c0 < 64) ? f[(size_t)n0 * 64 + c0]
                                : Fg[(size_t)n0 * 64 + (c0 - 64)];
            if (n1 < N_NODES)
                pf1 = (c1 < 64) ? f[(size_t)n1 * 64 + c1]
                                : Fg[(size_t)n1 * 64 + (c1 - 64)];
        }

        // ---- stage 1: 11 left contractions x NPB nodes ----
        #pragma unroll
        for (int nn = 0; nn < NPB; ++nn) {
            const u64* fp = sfd[buf][nn];
            u64 a0 = 0, a1 = 0;
            u64 a2x = 0, a2y = 0, a2z = 0;
            u64 a3x = 0, a3y = 0, a3z = 0;
            u64 a4x = 0, a4y = 0, a4z = 0;
            #pragma unroll
            for (int j = 0; j < 8; ++j) {
                int u = uh * 8 + j;
                u64 su = fp[u];
                u64 vx = fp[16 + u * 3 + 0];
                u64 vy = fp[16 + u * 3 + 1];
                u64 vz = fp[16 + u * 3 + 2];
                a0  = ffma2(su, wr[0][j], a0);
                a1  = ffma2(su, wr[1][j], a1);
                a2x = ffma2(vx, wr[2][j], a2x);
                a2y = ffma2(vy, wr[2][j], a2y);
                a2z = ffma2(vz, wr[2][j], a2z);
                a3x = ffma2(vx, wr[3][j], a3x);
                a3y = ffma2(vy, wr[3][j], a3y);
                a3z = ffma2(vz, wr[3][j], a3z);
                a4x = ffma2(vx, wr[4][j], a4x);
                a4y = ffma2(vy, wr[4][j], a4y);
                a4z = ffma2(vz, wr[4][j], a4z);
            }
            a0  = addf2(a0,  __shfl_xor_sync(0xffffffffu, a0,  1));
            a1  = addf2(a1,  __shfl_xor_sync(0xffffffffu, a1,  1));
            a2x = addf2(a2x, __shfl_xor_sync(0xffffffffu, a2x, 1));
            a2y = addf2(a2y, __shfl_xor_sync(0xffffffffu, a2y, 1));
            a2z = addf2(a2z, __shfl_xor_sync(0xffffffffu, a2z, 1));
            a3x = addf2(a3x, __shfl_xor_sync(0xffffffffu, a3x, 1));
            a3y = addf2(a3y, __shfl_xor_sync(0xffffffffu, a3y, 1));
            a3z = addf2(a3z, __shfl_xor_sync(0xffffffffu, a3z, 1));
            a4x = addf2(a4x, __shfl_xor_sync(0xffffffffu, a4x, 1));
            a4y = addf2(a4y, __shfl_xor_sync(0xffffffffu, a4y, 1));
            a4z = addf2(a4z, __shfl_xor_sync(0xffffffffu, a4z, 1));
            if (uh == 0) {
                tsp[nn][0][sl] = a0;  tsp[nn][1][sl] = a1;
                tsp[nn][2][sl] = a2x; tsp[nn][3][sl] = a2y; tsp[nn][4][sl] = a2z;
                tsp[nn][5][sl] = a3x; tsp[nn][6][sl] = a3y; tsp[nn][7][sl] = a3z;
                tsp[nn][8][sl] = a4x; tsp[nn][9][sl] = a4y; tsp[nn][10][sl] = a4z;
            }
        }
        __syncthreads();

        // ---- stage 2: NPB nodes x 32 output-pairs; 2 tasks/thread ----
        {
            const int t7 = t8 & 127;
            const int op = t7 >> 2, q = t7 & 3;
            const int ph = t8 >> 7;
            #pragma unroll
            for (int pp = 0; pp < 2; ++pp) {
                const int p = ph + 2 * pp;          // node 0..3
                const u64* SD = sfd[buf][p] + 64;
                const u64* VD = sfd[buf][p] + 80;
                const u64 (*tp)[TSTR] = tsp[p];
                u64 acc = 0;
                if (op < 8) {
                    const int wp2 = op;
                    u64 accd = 0;
                    #pragma unroll
                    for (int dv = 0; dv < 4; ++dv) {
                        int vv = q * 4 + dv;
                        int ti = vv * 9 + wp2;
                        acc  = ffma2(tp[0][ti], SD[vv], acc);
                        accd = ffma2(tp[5][ti], VD[vv * 3 + 0], accd);
                        accd = ffma2(tp[6][ti], VD[vv * 3 + 1], accd);
                        accd = ffma2(tp[7][ti], VD[vv * 3 + 2], accd);
                    }
                    acc = ffma2(accd, INV3p, acc);
                } else {
                    const int vo = op - 8;
                    const int wp2 = vo / 3, kk = vo % 3;
                    const int i = (kk + 1) % 3, j = (kk + 2) % 3;
                    u64 acc5 = 0;
                    #pragma unroll
                    for (int dv = 0; dv < 4; ++dv) {
                        int vv = q * 4 + dv;
                        int ti = vv * 9 + wp2;
                        acc  = ffma2(tp[1][ti], VD[vv * 3 + kk], acc);
                        acc  = ffma2(tp[2 + kk][ti], SD[vv], acc);
                        acc5 = ffma2(tp[8 + i][ti], VD[vv * 3 + j], acc5);
                        acc5 = ffma2(neg2(tp[8 + j][ti]), VD[vv * 3 + i], acc5);
                    }
                    acc = ffma2(acc5, INV2p, acc);
                }
                acc = addf2(acc, __shfl_xor_sync(0xffffffffu, acc, 1));
                acc = addf2(acc, __shfl_xor_sync(0xffffffffu, acc, 2));
                if (q == 0) {
                    float lo, hi;
                    unpack2f(lo, hi, acc);
                    float* ob = outb + p * 64;
                    if (op < 8) {
                        ob[2 * op]     = lo;
                        ob[2 * op + 1] = hi;
                    } else {
                        const int vo = op - 8;
                        const int wp2 = vo / 3, kk = vo % 3;
                        ob[16 + (2 * wp2) * 3 + kk]     = lo;
                        ob[16 + (2 * wp2 + 1) * 3 + kk] = hi;
                    }
                }
            }
        }
        __syncthreads();

        // ---- gate + writeback (NPB x 64 = 256 threads) + prefetch store ----
        {
            const int nn = t8 >> 6, oo = t8 & 63;
            const float* ob = outb + nn * 64;
            int node = base + nn;
            if (node < N_NODES) {
                float raw = ob[oo];
                float r;
                if (oo < 16) {
                    float sp = NORM_S * raw;
                    float sg = 1.f / (1.f + expf(-sp));
                    r = sp * sg;
                } else {
                    int w = (oo - 16) / 3;
                    float sp = NORM_S * ob[w];
                    float sg = 1.f / (1.f + expf(-sp));
                    r = NORM_V * raw * sg;
                }
                fout[(size_t)node * 64 + oo] = r;
            }
            // store prefetched features into alternate buffer; zero their Fg
            int idx0 = t8, idx1 = 256 + t8;
            int p0 = idx0 >> 7, c0 = idx0 & 127;
            int p1 = idx1 >> 7, c1 = idx1 & 127;
            sfd[buf ^ 1][p0][c0] = pack2f(pf0, pf0);
            sfd[buf ^ 1][p1][c1] = pack2f(pf1, pf1);
            int n0 = nbase + p0, n1 = nbase + p1;
            if (n0 < N_NODES && c0 >= 64) Fg[(size_t)n0 * 64 + (c0 - 64)] = 0.f;
            if (n1 < N_NODES && c1 >= 64) Fg[(size_t)n1 * 64 + (c1 - 64)] = 0.f;
        }
        __syncthreads();
    }
}

// ---------------------------------------------------------------------------
// Readout: energy[g] = sum_n (s[n]·w_out) * 0.25   grouped by batch_idx
// ---------------------------------------------------------------------------
__global__ __launch_bounds__(256) void readout_kernel(
    const float* __restrict__ f, const int* __restrict__ batch,
    const float* __restrict__ w, float* __restrict__ out)
{
    __shared__ float acc[N_GRAPHS];
    __shared__ float sw[16];
    int t = threadIdx.x;
    if (t < N_GRAPHS) acc[t] = 0.f;
    if (t < 16) sw[t] = w[t];
    __syncthreads();
    int n = blockIdx.x * 256 + t;
    if (n < N_NODES) {
        const float* fn = f + (size_t)n * 64;
        float val = 0.f;
        #pragma unroll
        for (int u = 0; u < 16; ++u) val += fn[u] * sw[u];
        atomicAdd(&acc[batch[n]], val * INV_LIN_OUT);
    }
    __syncthreads();
    if (t < N_GRAPHS && acc[t] != 0.f) atomicAdd(out + t, acc[t]);
}

// ---------------------------------------------------------------------------
extern "C" void kernel_launch(void* const* d_in, const int* in_sizes, int n_in,
                              void* d_out, int out_size)
{
    const float* x      = (const float*)d_in[0];
    const int*   row    = (const int*)  d_in[1];
    const int*   col    = (const int*)  d_in[2];
    const int*   batch  = (const int*)  d_in[3];
    const float* w_in0  = (const float*)d_in[4];
    const float* w_in1  = (const float*)d_in[5];
    const float* tpw    = (const float*)d_in[6];
    const float* w_out0 = (const float*)d_in[7];
    float* out = (float*)d_out;

    float *fa, *fb, *Fg;
    cudaGetSymbolAddress((void**)&fa, g_fa);
    cudaGetSymbolAddress((void**)&fb, g_fb);
    cudaGetSymbolAddress((void**)&Fg, g_F);

    cudaFuncSetAttribute(tp_gate_kernel,
                         cudaFuncAttributeMaxDynamicSharedMemorySize, SM_BYTES);

    proj_kernel<<<(N_NODES + 255) / 256, 256>>>(x, w_in0, w_in1, fa);

    float* cur = fa;
    float* nxt = fb;
    for (int l = 0; l < 3; ++l) {
        agg_kernel<<<(N_EDGES * 16 + 255) / 256, 256>>>(cur, row, col, Fg);
        tp_gate_kernel<<<296, 256, SM_BYTES>>>(cur, Fg, tpw + (size_t)l * 5 * 4096, nxt);
        float* tmp = cur; cur = nxt; nxt = tmp;
    }

    cudaMemsetAsync(out, 0, N_GRAPHS * sizeof(float));
    readout_kernel<<<(N_NODES + 255) / 256, 256>>>(cur, batch, w_out0, out);
}

// round 17
// speedup vs baseline: 1.8256x; 1.0264x over previous
#include <cuda_runtime.h>
#include <math.h>

#define N_NODES 50000
#define N_EDGES 600000
#define N_GRAPHS 64

static __device__ float g_fa[N_NODES * 64];
static __device__ float g_fb[N_NODES * 64];
static __device__ float g_F [N_NODES * 64];   // zero-init at load; kernel re-zeroes after use

#define INV_S3 0.57735026918962576f   /* 1/sqrt(3) */
#define INV_S2 0.70710678118654752f   /* 1/sqrt(2) */
#define NORM_S 0.044194173824159216f  /* 1/sqrt(512) */
#define NORM_V 0.036084391824351615f  /* 1/sqrt(768) */
#define INV_LIN_IN 0.35355339059327373f /* 1/sqrt(8) */
#define INV_LIN_OUT 0.25f

typedef unsigned long long u64;

// ---- packed fp32x2 helpers (sm_103a) --------------------------------------
__device__ __forceinline__ u64 pack2f(float a, float b) {
    u64 r;
    asm("mov.b64 %0, {%1, %2};" : "=l"(r) : "f"(a), "f"(b));
    return r;
}
__device__ __forceinline__ void unpack2f(float& a, float& b, u64 p) {
    asm("mov.b64 {%0, %1}, %2;" : "=f"(a), "=f"(b) : "l"(p));
}
__device__ __forceinline__ u64 ffma2(u64 a, u64 b, u64 c) {
    u64 d;
    asm("fma.rn.f32x2 %0, %1, %2, %3;" : "=l"(d) : "l"(a), "l"(b), "l"(c));
    return d;
}
__device__ __forceinline__ u64 addf2(u64 a, u64 b) {
    u64 d;
    asm("add.rn.f32x2 %0, %1, %2;" : "=l"(d) : "l"(a), "l"(b));
    return d;
}
__device__ __forceinline__ u64 neg2(u64 a) { return a ^ 0x8000000080000000ULL; }

__device__ __forceinline__ float fast_sigmoid(float x) {
    return 1.f / (1.f + __expf(-x));
}

// ---------------------------------------------------------------------------
// zero_out: clears the 64-float output buffer. Launched FIRST so that ncu's
// fixed "-s 5 -c 1" capture lands on tp_gate_kernel (launch index 5) instead
// of agg_kernel.
// ---------------------------------------------------------------------------
__global__ void zero_out_kernel(float* __restrict__ out) {
    if (threadIdx.x < N_GRAPHS) out[threadIdx.x] = 0.f;
}

// ---------------------------------------------------------------------------
// Input projection: x[N,32] -> f[N,64]  (s[16] | v[16][3] at 16+w*3+i)
// ---------------------------------------------------------------------------
__global__ __launch_bounds__(256) void proj_kernel(
    const float* __restrict__ x, const float* __restrict__ w0,
    const float* __restrict__ w1, float* __restrict__ f)
{
    __shared__ float sw0[128], sw1[128];
    int t = threadIdx.x;
    if (t < 128) sw0[t] = w0[t];
    else         sw1[t - 128] = w1[t - 128];
    __syncthreads();

    int n = blockIdx.x * 256 + t;
    if (n >= N_NODES) return;

    float xin[32];
    #pragma unroll
    for (int i = 0; i < 8; ++i)
        ((float4*)xin)[i] = ((const float4*)(x + n * 32))[i];

    float s[16];
    #pragma unroll
    for (int w = 0; w < 16; ++w) s[w] = 0.f;
    #pragma unroll
    for (int u = 0; u < 8; ++u) {
        float xu = xin[u];
        #pragma unroll
        for (int w = 0; w < 16; ++w) s[w] += xu * sw0[u * 16 + w];
    }
    float vv[48];
    #pragma unroll
    for (int q = 0; q < 48; ++q) vv[q] = 0.f;
    #pragma unroll
    for (int u = 0; u < 8; ++u) {
        float x0 = xin[8 + u * 3 + 0];
        float x1 = xin[8 + u * 3 + 1];
        float x2 = xin[8 + u * 3 + 2];
        #pragma unroll
        for (int w = 0; w < 16; ++w) {
            float wt = sw1[u * 16 + w];
            vv[w * 3 + 0] += x0 * wt;
            vv[w * 3 + 1] += x1 * wt;
            vv[w * 3 + 2] += x2 * wt;
        }
    }
    float* fn = f + n * 64;
    #pragma unroll
    for (int w = 0; w < 16; ++w) fn[w] = s[w] * INV_LIN_IN;
    #pragma unroll
    for (int q = 0; q < 48; ++q) fn[16 + q] = vv[q] * INV_LIN_IN;
}

// ---------------------------------------------------------------------------
// Aggregation: F[row[e]] += f[col[e]] via red.global.v4.f32.add (REDG.128)
// ---------------------------------------------------------------------------
__global__ __launch_bounds__(256) void agg_kernel(
    const float* __restrict__ f, const int* __restrict__ row,
    const int* __restrict__ col, float* __restrict__ F)
{
    unsigned idx = blockIdx.x * 256u + threadIdx.x;
    unsigned e = idx >> 4, q = idx & 15u;
    if (e >= N_EDGES) return;
    int c = __ldg(col + e);
    int r = __ldg(row + e);
    float4 val = ((const float4*)(f + (size_t)c * 64))[q];
    float* dst = F + (size_t)r * 64 + q * 4;
    asm volatile("red.global.v4.f32.add [%0], {%1, %2, %3, %4};"
                 :: "l"(dst), "f"(val.x), "f"(val.y), "f"(val.z), "f"(val.w)
                 : "memory");
}

// ---------------------------------------------------------------------------
// Per-node TP + gate: (v,w)-pair f32x2 packing with u-split lane pairs,
// NPB=4 nodes/iteration, register-carried feature prefetch (single smem
// buffer), Fg self-zeroing. Thread t8 = slot*2 + uh, slot = v*8 + wp; all
// 5 weight paths in registers (40 u64). Stage-1 partials combine via
// shfl_xor(1); STS of the 11 contraction rows split across uh halves.
//
// Shared memory map (u64 units):
//   sfd : u64[NPB][128]      = 4*128    =  512
//   tsp : u64[NPB][11][TSTR] = 4*11*144 = 6336
//   outb: float[NPB][64]     = 256 f    =  128 u64
// ---------------------------------------------------------------------------
#define NPB 4
#define TSTR 144   /* 16 * 9, padded stride */

#define SMU_SFD  0
#define SMU_TSP  (SMU_SFD + NPB * 128)                /* 512 */
#define SMU_OUT  (SMU_TSP + NPB * 11 * TSTR)          /* 512 + 6336 */
#define SMU_TOT  (SMU_OUT + (NPB * 64 * 4 + 7) / 8)   /* + 128 u64 */
#define SM_BYTES (SMU_TOT * 8)

__global__ __launch_bounds__(256, 2) void tp_gate_kernel(
    const float* __restrict__ f, float* __restrict__ Fg,
    const float* __restrict__ W, float* __restrict__ fout)
{
    extern __shared__ u64 dsm[];
    u64 (*sfd)[128]      = (u64 (*)[128])(dsm + SMU_SFD);
    u64 (*tsp)[11][TSTR] = (u64 (*)[11][TSTR])(dsm + SMU_TSP);
    float* outb          = (float*)(dsm + SMU_OUT);

    const int t8   = threadIdx.x;
    const int slot = t8 >> 1;        // v*8 + wp
    const int uh   = t8 & 1;         // u half
    const int v    = slot >> 3;
    const int wp   = slot & 7;
    const int sl   = v * 9 + wp;     // padded tsp slot

    // ---- weight preload: 5 paths x 8 u, packed (w=2wp, 2wp+1) ----
    const float2* Wf2 = (const float2*)W;
    u64 wr[5][8];
    #pragma unroll
    for (int p = 0; p < 5; ++p)
        #pragma unroll
        for (int j = 0; j < 8; ++j) {
            float2 a = __ldg(Wf2 + p * 2048 + (uh * 8 + j) * 128 + slot);
            wr[p][j] = pack2f(a.x, a.y);
        }

    const u64 INV3p = pack2f(INV_S3, INV_S3);
    const u64 INV2p = pack2f(INV_S2, INV_S2);
    const int stride = gridDim.x * NPB;

    // ---- initial feature load (+ Fg zeroing) into sfd ----
    int base = blockIdx.x * NPB;
    {
        #pragma unroll
        for (int k = 0; k < 2; ++k) {
            int idx = k * 256 + t8;
            int nn = idx >> 7, c = idx & 127;
            int node = base + nn;
            float val = 0.f;
            if (node < N_NODES) {
                if (c < 64) val = f[(size_t)node * 64 + c];
                else {
                    val = Fg[(size_t)node * 64 + (c - 64)];
                    Fg[(size_t)node * 64 + (c - 64)] = 0.f;
                }
            }
            sfd[nn][c] = pack2f(val, val);
        }
    }
    __syncthreads();

    for (; base < N_NODES; base += stride) {
        const int nbase = base + stride;

        // ---- prefetch next iteration's features (LDG only, regs) ----
        float pf0 = 0.f, pf1 = 0.f;
        {
            int idx0 = t8, idx1 = 256 + t8;
            int n0 = nbase + (idx0 >> 7), c0 = idx0 & 127;
            int n1 = nbase + (idx1 >> 7), c1 = idx1 & 127;
            if (n0 < N_NODES)
                pf0 = (c0 < 64) ? f[(size_t)n0 * 64 + c0]
                                : Fg[(size_t)n0 * 64 + (c0 - 64)];
            if (n1 < N_NODES)
                pf1 = (c1 < 64) ? f[(size_t)n1 * 64 + c1]
                                : Fg[(size_t)n1 * 64 + (c1 - 64)];
        }

        // ---- stage 1: 11 left contractions x NPB nodes ----
        #pragma unroll
        for (int nn = 0; nn < NPB; ++nn) {
            const u64* fp = sfd[nn];
            u64 a0 = 0, a1 = 0;
            u64 a2x = 0, a2y = 0, a2z = 0;
            u64 a3x = 0, a3y = 0, a3z = 0;
            u64 a4x = 0, a4y = 0, a4z = 0;
            #pragma unroll
            for (int j = 0; j < 8; ++j) {
                int u = uh * 8 + j;
                u64 su = fp[u];
                u64 vx = fp[16 + u * 3 + 0];
                u64 vy = fp[16 + u * 3 + 1];
                u64 vz = fp[16 + u * 3 + 2];
                a0  = ffma2(su, wr[0][j], a0);
                a1  = ffma2(su, wr[1][j], a1);
                a2x = ffma2(vx, wr[2][j], a2x);
                a2y = ffma2(vy, wr[2][j], a2y);
                a2z = ffma2(vz, wr[2][j], a2z);
                a3x = ffma2(vx, wr[3][j], a3x);
                a3y = ffma2(vy, wr[3][j], a3y);
                a3z = ffma2(vz, wr[3][j], a3z);
                a4x = ffma2(vx, wr[4][j], a4x);
                a4y = ffma2(vy, wr[4][j], a4y);
                a4z = ffma2(vz, wr[4][j], a4z);
            }
            a0  = addf2(a0,  __shfl_xor_sync(0xffffffffu, a0,  1));
            a1  = addf2(a1,  __shfl_xor_sync(0xffffffffu, a1,  1));
            a2x = addf2(a2x, __shfl_xor_sync(0xffffffffu, a2x, 1));
            a2y = addf2(a2y, __shfl_xor_sync(0xffffffffu, a2y, 1));
            a2z = addf2(a2z, __shfl_xor_sync(0xffffffffu, a2z, 1));
            a3x = addf2(a3x, __shfl_xor_sync(0xffffffffu, a3x, 1));
            a3y = addf2(a3y, __shfl_xor_sync(0xffffffffu, a3y, 1));
            a3z = addf2(a3z, __shfl_xor_sync(0xffffffffu, a3z, 1));
            a4x = addf2(a4x, __shfl_xor_sync(0xffffffffu, a4x, 1));
            a4y = addf2(a4y, __shfl_xor_sync(0xffffffffu, a4y, 1));
            a4z = addf2(a4z, __shfl_xor_sync(0xffffffffu, a4z, 1));
            // split the 11 STS across uh halves (both have full sums)
            if (uh == 0) {
                tsp[nn][0][sl] = a0;  tsp[nn][1][sl] = a1;
                tsp[nn][2][sl] = a2x; tsp[nn][3][sl] = a2y;
                tsp[nn][4][sl] = a2z; tsp[nn][5][sl] = a3x;
            } else {
                tsp[nn][6][sl] = a3y; tsp[nn][7][sl] = a3z;
                tsp[nn][8][sl] = a4x; tsp[nn][9][sl] = a4y;
                tsp[nn][10][sl] = a4z;
            }
        }
        __syncthreads();

        // ---- stage 2: NPB nodes x 32 output-pairs; 2 tasks/thread ----
        {
            const int t7 = t8 & 127;
            const int op = t7 >> 2, q = t7 & 3;
            const int ph = t8 >> 7;
            #pragma unroll
            for (int pp = 0; pp < 2; ++pp) {
                const int p = ph + 2 * pp;          // node 0..3
                const u64* SD = sfd[p] + 64;
                const u64* VD = sfd[p] + 80;
                const u64 (*tp)[TSTR] = tsp[p];
                u64 acc = 0;
                if (op < 8) {
                    const int wp2 = op;
                    u64 accd = 0;
                    #pragma unroll
                    for (int dv = 0; dv < 4; ++dv) {
                        int vv = q * 4 + dv;
                        int ti = vv * 9 + wp2;
                        acc  = ffma2(tp[0][ti], SD[vv], acc);
                        accd = ffma2(tp[5][ti], VD[vv * 3 + 0], accd);
                        accd = ffma2(tp[6][ti], VD[vv * 3 + 1], accd);
                        accd = ffma2(tp[7][ti], VD[vv * 3 + 2], accd);
                    }
                    acc = ffma2(accd, INV3p, acc);
                } else {
                    const int vo = op - 8;
                    const int wp2 = vo / 3, kk = vo % 3;
                    const int i = (kk + 1) % 3, j = (kk + 2) % 3;
                    u64 acc5 = 0;
                    #pragma unroll
                    for (int dv = 0; dv < 4; ++dv) {
                        int vv = q * 4 + dv;
                        int ti = vv * 9 + wp2;
                        acc  = ffma2(tp[1][ti], VD[vv * 3 + kk], acc);
                        acc  = ffma2(tp[2 + kk][ti], SD[vv], acc);
                        acc5 = ffma2(tp[8 + i][ti], VD[vv * 3 + j], acc5);
                        acc5 = ffma2(neg2(tp[8 + j][ti]), VD[vv * 3 + i], acc5);
                    }
                    acc = ffma2(acc5, INV2p, acc);
                }
                acc = addf2(acc, __shfl_xor_sync(0xffffffffu, acc, 1));
                acc = addf2(acc, __shfl_xor_sync(0xffffffffu, acc, 2));
                if (q == 0) {
                    float lo, hi;
                    unpack2f(lo, hi, acc);
                    float* ob = outb + p * 64;
                    if (op < 8) {
                        ob[2 * op]     = lo;
                        ob[2 * op + 1] = hi;
                    } else {
                        const int vo = op - 8;
                        const int wp2 = vo / 3, kk = vo % 3;
                        ob[16 + (2 * wp2) * 3 + kk]     = lo;
                        ob[16 + (2 * wp2 + 1) * 3 + kk] = hi;
                    }
                }
            }
        }
        __syncthreads();

        // ---- gate + writeback (NPB x 64 = 256 threads) + prefetch store ----
        {
            const int nn = t8 >> 6, oo = t8 & 63;
            const float* ob = outb + nn * 64;
            int node = base + nn;
            if (node < N_NODES) {
                float raw = ob[oo];
                float r;
                if (oo < 16) {
                    float sp = NORM_S * raw;
                    r = sp * fast_sigmoid(sp);
                } else {
                    int w = (oo - 16) / 3;
                    float sp = NORM_S * ob[w];
                    r = NORM_V * raw * fast_sigmoid(sp);
                }
                fout[(size_t)node * 64 + oo] = r;
            }
            // store prefetched features into sfd (stage-2 done reading);
            // zero their Fg slots
            int idx0 = t8, idx1 = 256 + t8;
            int p0 = idx0 >> 7, c0 = idx0 & 127;
            int p1 = idx1 >> 7, c1 = idx1 & 127;
            sfd[p0][c0] = pack2f(pf0, pf0);
            sfd[p1][c1] = pack2f(pf1, pf1);
            int n0 = nbase + p0, n1 = nbase + p1;
            if (n0 < N_NODES && c0 >= 64) Fg[(size_t)n0 * 64 + (c0 - 64)] = 0.f;
            if (n1 < N_NODES && c1 >= 64) Fg[(size_t)n1 * 64 + (c1 - 64)] = 0.f;
        }
        __syncthreads();
    }
}

// ---------------------------------------------------------------------------
// Readout: energy[g] = sum_n (s[n]·w_out) * 0.25   grouped by batch_idx
// ---------------------------------------------------------------------------
__global__ __launch_bounds__(256) void readout_kernel(
    const float* __restrict__ f, const int* __restrict__ batch,
    const float* __restrict__ w, float* __restrict__ out)
{
    __shared__ float acc[N_GRAPHS];
    __shared__ float sw[16];
    int t = threadIdx.x;
    if (t < N_GRAPHS) acc[t] = 0.f;
    if (t < 16) sw[t] = w[t];
    __syncthreads();
    int n = blockIdx.x * 256 + t;
    if (n < N_NODES) {
        const float* fn = f + (size_t)n * 64;
        float val = 0.f;
        #pragma unroll
        for (int u = 0; u < 16; ++u) val += fn[u] * sw[u];
        atomicAdd(&acc[batch[n]], val * INV_LIN_OUT);
    }
    __syncthreads();
    if (t < N_GRAPHS && acc[t] != 0.f) atomicAdd(out + t, acc[t]);
}

// ---------------------------------------------------------------------------
extern "C" void kernel_launch(void* const* d_in, const int* in_sizes, int n_in,
                              void* d_out, int out_size)
{
    const float* x      = (const float*)d_in[0];
    const int*   row    = (const int*)  d_in[1];
    const int*   col    = (const int*)  d_in[2];
    const int*   batch  = (const int*)  d_in[3];
    const float* w_in0  = (const float*)d_in[4];
    const float* w_in1  = (const float*)d_in[5];
    const float* tpw    = (const float*)d_in[6];
    const float* w_out0 = (const float*)d_in[7];
    float* out = (float*)d_out;

    float *fa, *fb, *Fg;
    cudaGetSymbolAddress((void**)&fa, g_fa);
    cudaGetSymbolAddress((void**)&fb, g_fb);
    cudaGetSymbolAddress((void**)&Fg, g_F);

    cudaFuncSetAttribute(tp_gate_kernel,
                         cudaFuncAttributeMaxDynamicSharedMemorySize, SM_BYTES);

    // launch 0: zero the output (also shifts ncu -s 5 onto tp_gate at idx 5)
    zero_out_kernel<<<1, 64>>>(out);

    proj_kernel<<<(N_NODES + 255) / 256, 256>>>(x, w_in0, w_in1, fa);

    float* cur = fa;
    float* nxt = fb;
    for (int l = 0; l < 3; ++l) {
        agg_kernel<<<(N_EDGES * 16 + 255) / 256, 256>>>(cur, row, col, Fg);
        tp_gate_kernel<<<296, 256, SM_BYTES>>>(cur, Fg, tpw + (size_t)l * 5 * 4096, nxt);
        float* tmp = cur; cur = nxt; nxt = tmp;
    }

    readout_kernel<<<(N_NODES + 255) / 256, 256>>>(cur, batch, w_out0, out);
}